// round 1
// baseline (speedup 1.0000x reference)
#include <cuda_runtime.h>

#define NN 100000
#define EE 1600000
#define EPSF 1e-12f

// ---------------- scratch (static device globals; no allocation allowed) ----
__device__ __align__(128) float g_outdeg[NN];
__device__ __align__(128) float g_indeg[NN];
__device__ __align__(128) float g_deg[NN];
__device__ __align__(128) float g_h[NN * 64];    // transformed features (pre-aggregation)
__device__ __align__(128) float g_agg[NN * 64];  // aggregation accumulator
__device__ __align__(128) float g_t1[NN * 64];   // layer-1 output
__device__ __align__(128) float g_t2[NN * 32];   // layer-2 output

// ---------------- zero: degrees + agg ---------------------------------------
__global__ void zero_kernel() {
    int i = blockIdx.x * blockDim.x + threadIdx.x;
    if (i < NN) { g_outdeg[i] = 0.f; g_indeg[i] = 0.f; g_deg[i] = 0.f; }
    if (i < NN * 64) g_agg[i] = 0.f;
}

// ---------------- edge-weight degree sums -----------------------------------
__global__ void edge_deg_kernel(const int* __restrict__ src,
                                const int* __restrict__ dst,
                                const float* __restrict__ w) {
    int e = blockIdx.x * blockDim.x + threadIdx.x;
    if (e >= EE) return;
    float wv = w[e];
    atomicAdd(&g_outdeg[src[e]], wv);
    atomicAdd(&g_indeg[dst[e]], wv);
}

// ---------------- dense GEMM: h = x @ W (W in shared, 4 cols/thread) --------
// srcSel: 0 -> xext, 1 -> g_t1, 2 -> g_t2
template <int DIN, int DOUT>
__global__ void gemm_kernel(const float* __restrict__ xext,
                            const float* __restrict__ W, int srcSel) {
    __shared__ float sW[DIN * DOUT];
    for (int i = threadIdx.x; i < DIN * DOUT; i += blockDim.x) sW[i] = W[i];
    __syncthreads();

    const float* x = (srcSel == 0) ? xext : (srcSel == 1) ? g_t1 : g_t2;

    constexpr int TPR = DOUT / 4;            // threads per row
    const int rowsPerBlock = blockDim.x / TPR;
    int row = blockIdx.x * rowsPerBlock + threadIdx.x / TPR;
    int cg  = (threadIdx.x % TPR) * 4;       // first output column
    if (row >= NN) return;

    float a0 = 0.f, a1 = 0.f, a2 = 0.f, a3 = 0.f;
    const float4* x4 = reinterpret_cast<const float4*>(x + (size_t)row * DIN);
#pragma unroll
    for (int k4 = 0; k4 < DIN / 4; k4++) {
        float4 xv = __ldg(&x4[k4]);
#pragma unroll
        for (int j = 0; j < 4; j++) {
            float xs = (j == 0) ? xv.x : (j == 1) ? xv.y : (j == 2) ? xv.z : xv.w;
            const float4 wv = *reinterpret_cast<const float4*>(&sW[(k4 * 4 + j) * DOUT + cg]);
            a0 += xs * wv.x; a1 += xs * wv.y; a2 += xs * wv.z; a3 += xs * wv.w;
        }
    }
    float4* h4 = reinterpret_cast<float4*>(g_h + (size_t)row * DOUT);
    h4[cg / 4] = make_float4(a0, a1, a2, a3);
}

// ---------------- fused norm + weighted-degree + scatter ---------------------
// 32 edges per warp: coalesced index loads, shfl-broadcast, full-warp payload.
template <int DOUT>
__global__ void scatter_kernel(const int* __restrict__ src,
                               const int* __restrict__ dst,
                               const float* __restrict__ w) {
    int lane = threadIdx.x & 31;
    int warpId = (blockIdx.x * blockDim.x + threadIdx.x) >> 5;
    int base = warpId * 32;
    if (base >= EE) return;

    int s = 0, d = 0; float nw = 0.f;
    int e = base + lane;
    if (e < EE) {
        s = src[e]; d = dst[e];
        float wv = w[e];
        nw = wv * rsqrtf(fmaxf(g_outdeg[s] * g_indeg[d], EPSF));
        atomicAdd(&g_deg[d], nw);
    }
#pragma unroll 1
    for (int i = 0; i < 32; i++) {
        int   ss = __shfl_sync(0xffffffffu, s,  i);
        int   dd = __shfl_sync(0xffffffffu, d,  i);
        float nn = __shfl_sync(0xffffffffu, nw, i);
        if (base + i < EE) {
#pragma unroll
            for (int f = 0; f < DOUT; f += 32) {
                float hv = __ldg(&g_h[(size_t)ss * DOUT + f + lane]);
                atomicAdd(&g_agg[(size_t)dd * DOUT + f + lane], hv * nn);
            }
        }
    }
}

// ---------------- finalize: out = agg / max(deg,eps) + b --------------------
// dstSel: 0 -> outext, 1 -> g_t1, 2 -> g_t2
template <int DOUT>
__global__ void finalize_kernel(const float* __restrict__ b,
                                float* __restrict__ outext, int dstSel) {
    int idx = blockIdx.x * blockDim.x + threadIdx.x;
    if (idx >= NN * DOUT) return;
    float* out = (dstSel == 0) ? outext : (dstSel == 1) ? g_t1 : g_t2;
    int i = idx / DOUT;
    int f = idx % DOUT;
    out[idx] = g_agg[idx] / fmaxf(g_deg[i], EPSF) + __ldg(&b[f]);
}

// ---------------- launch ------------------------------------------------------
extern "C" void kernel_launch(void* const* d_in, const int* in_sizes, int n_in,
                              void* d_out, int out_size) {
    const float* x    = (const float*)d_in[0];
    const int*   src1 = (const int*)d_in[1];
    const int*   dst1 = (const int*)d_in[2];
    const float* w1   = (const float*)d_in[3];
    const int*   src2 = (const int*)d_in[4];
    const int*   dst2 = (const int*)d_in[5];
    const float* w2   = (const float*)d_in[6];
    const int*   src3 = (const int*)d_in[7];
    const int*   dst3 = (const int*)d_in[8];
    const float* w3   = (const float*)d_in[9];
    const float* W1   = (const float*)d_in[10];
    const float* b1   = (const float*)d_in[11];
    const float* W2   = (const float*)d_in[12];
    const float* b2   = (const float*)d_in[13];
    const float* W3   = (const float*)d_in[14];
    const float* b3   = (const float*)d_in[15];
    float* out = (float*)d_out;

    const int B = 256;
    const int gridZero  = (NN * 64 + B - 1) / B;
    const int gridEdge  = (EE + B - 1) / B;
    const int gridScat  = ((EE / 32) * 32 + (B / 32) * 32 - 1) / ((B / 32) * 32); // warps cover EE/32 groups
    const int gridScat2 = (EE / 32 + (B / 32) - 1) / (B / 32);

    // ---- Layer 1: 128 -> 64 ----
    zero_kernel<<<gridZero, B>>>();
    edge_deg_kernel<<<gridEdge, B>>>(src1, dst1, w1);
    gemm_kernel<128, 64><<<NN / (B / 16), B>>>(x, W1, 0);
    scatter_kernel<64><<<gridScat2, B>>>(src1, dst1, w1);
    finalize_kernel<64><<<(NN * 64 + B - 1) / B, B>>>(b1, nullptr, 1);

    // ---- Layer 2: 64 -> 32 ----
    zero_kernel<<<gridZero, B>>>();
    edge_deg_kernel<<<gridEdge, B>>>(src2, dst2, w2);
    gemm_kernel<64, 32><<<NN / (B / 8), B>>>(nullptr, W2, 1);
    scatter_kernel<32><<<gridScat2, B>>>(src2, dst2, w2);
    finalize_kernel<32><<<(NN * 32 + B - 1) / B, B>>>(b2, nullptr, 2);

    // ---- Layer 3: 32 -> 32 ----
    zero_kernel<<<gridZero, B>>>();
    edge_deg_kernel<<<gridEdge, B>>>(src3, dst3, w3);
    gemm_kernel<32, 32><<<NN / (B / 8), B>>>(nullptr, W3, 2);
    scatter_kernel<32><<<gridScat2, B>>>(src3, dst3, w3);
    finalize_kernel<32><<<(NN * 32 + B - 1) / B, B>>>(b3, out, 0);

    (void)gridScat; (void)in_sizes; (void)n_in; (void)out_size;
}